// round 1
// baseline (speedup 1.0000x reference)
#include <cuda_runtime.h>
#include <math.h>

// Problem dims
#define BATCH 8192
#define OBS 64
#define ACT 16
#define HID 128
#define CON 256
#define COMP 85
#define KS 32

// ---------------- scratch (device globals; no allocation) ----------------
__device__ float g_G[COMP * COMP];          // W1 W1^T
__device__ float g_fout[BATCH * COMP];      // f-net output (relu(p3))
__device__ float g_kout[BATCH];             // k-net output (softplus)
__device__ unsigned g_d1m[BATCH * 3];       // d1 bitmask (85 bits in 3 words)
__device__ unsigned g_d2m[BATCH * 3];       // d2 bitmask

// =========================================================================
// Kernel 1: G = mw1 @ mw1^T   (85x85, K=256)
// =========================================================================
__global__ void g_kernel(const float* __restrict__ mw1) {
    int gid = blockIdx.x * 256 + threadIdx.x;
    if (gid < COMP * COMP) {
        int i = gid / COMP;
        int j = gid - i * COMP;
        const float* a = mw1 + i * CON;
        const float* b = mw1 + j * CON;
        float acc = 0.f;
        #pragma unroll 8
        for (int k = 0; k < CON; k++) acc = fmaf(a[k], b[k], acc);
        g_G[gid] = acc;
    }
}

// =========================================================================
// Kernel 2: fused forward pass. 64 samples per CTA, 256 threads.
// Thread map: sp = tid>>3 owns samples {2sp, 2sp+1}; q = tid&7 owns
// output cols o = q + 8j.
// =========================================================================
#define TS 64

// smem layout (float offsets)
#define O_X   0            // x buffer 64 x 257 (concat of/af)
#define XS    257
#define O_W   16448        // weight staging 16512 floats
#define O_T   32960        // head layer-1 temp 64 x 129
#define TBS   129
#define O_IN  41216        // input staging 64 x 65 (also k1/k2 bufs)
#define O_K1  41216        // k1: 64 x 33
#define O_K2  43328        // k2: 64 x 17
#define O_H1  45376        // h1 / f_out: 64 x 87
#define O_H2  50944        // h2: 64 x 87
#define HS    87
#define FWD_SMEM_FLOATS 56512
#define FWD_SMEM_BYTES  (FWD_SMEM_FLOATS * 4)

#define ACT_RELU 0
#define ACT_TANH 1

template<int N, int ACTT>
__device__ __forceinline__ void layer_fwd(
    float* __restrict__ sm,
    int o_out, int outStride, int outColOff,
    int o_in, int inStride,
    const float* __restrict__ Wg, const float* __restrict__ bg, int K)
{
    constexpr int NJ = (N + 7) / 8;
    const int tid = threadIdx.x;
    const int sp = tid >> 3;
    const int q = tid & 7;
    const int s0 = sp * 2, s1 = s0 + 1;

    float acc0[NJ], acc1[NJ];
    #pragma unroll
    for (int j = 0; j < NJ; j++) { acc0[j] = 0.f; acc1[j] = 0.f; }

    float* wbuf = sm + O_W;

    for (int k0 = 0; k0 < K; k0 += 128) {
        int KC = K - k0; if (KC > 128) KC = 128;
        int WS = (KC & 1) ? KC : (KC + 1);   // odd stride -> conflict-free
        __syncthreads();
        for (int i = tid; i < N * KC; i += 256) {
            int r = i / KC;
            int c = i - r * KC;
            wbuf[r * WS + c] = Wg[r * K + k0 + c];
        }
        __syncthreads();
        const float* in0 = sm + o_in + s0 * inStride + k0;
        const float* in1 = sm + o_in + s1 * inStride + k0;
        for (int k = 0; k < KC; k++) {
            float a0 = in0[k];
            float a1 = in1[k];
            const float* wr = wbuf + k + q * WS;
            #pragma unroll
            for (int j = 0; j < NJ; j++) {
                float w = wr[(j << 3) * WS];
                acc0[j] = fmaf(a0, w, acc0[j]);
                acc1[j] = fmaf(a1, w, acc1[j]);
            }
        }
    }
    #pragma unroll
    for (int j = 0; j < NJ; j++) {
        int o = q + (j << 3);
        if (o < N) {
            float bv = bg[o];
            float v0 = acc0[j] + bv;
            float v1 = acc1[j] + bv;
            if (ACTT == ACT_RELU) { v0 = fmaxf(v0, 0.f); v1 = fmaxf(v1, 0.f); }
            else if (ACTT == ACT_TANH) { v0 = tanhf(v0); v1 = tanhf(v1); }
            sm[o_out + s0 * outStride + outColOff + o] = v0;
            sm[o_out + s1 * outStride + outColOff + o] = v1;
        }
    }
    __syncthreads();
}

__global__ __launch_bounds__(256)
void fwd_kernel(
    const float* __restrict__ obs, const float* __restrict__ action,
    const float* __restrict__ ow1, const float* __restrict__ ob1,
    const float* __restrict__ ow2, const float* __restrict__ ob2,
    const float* __restrict__ aw1, const float* __restrict__ ab1,
    const float* __restrict__ aw2, const float* __restrict__ ab2,
    const float* __restrict__ mw1, const float* __restrict__ mb1,
    const float* __restrict__ mw2, const float* __restrict__ mb2,
    const float* __restrict__ mw3, const float* __restrict__ mb3,
    const float* __restrict__ kw1, const float* __restrict__ kb1,
    const float* __restrict__ kw2, const float* __restrict__ kb2,
    const float* __restrict__ kw3, const float* __restrict__ kb3)
{
    extern __shared__ float sm[];
    const int tid = threadIdx.x;
    const int sbase = blockIdx.x * TS;

    // ---- obs head ----
    for (int i = tid; i < TS * OBS; i += 256) {
        int s = i >> 6, k = i & 63;
        sm[O_IN + s * 65 + k] = obs[(sbase + s) * OBS + k];
    }
    __syncthreads();
    layer_fwd<HID, ACT_RELU>(sm, O_T, TBS, 0, O_IN, 65, ow1, ob1, OBS);
    layer_fwd<HID, ACT_RELU>(sm, O_X, XS, 0, O_T, TBS, ow2, ob2, HID);

    // ---- action head ----
    for (int i = tid; i < TS * ACT; i += 256) {
        int s = i >> 4, k = i & 15;
        sm[O_IN + s * 17 + k] = action[(sbase + s) * ACT + k];
    }
    __syncthreads();
    layer_fwd<HID, ACT_RELU>(sm, O_T, TBS, 0, O_IN, 17, aw1, ab1, ACT);
    layer_fwd<HID, ACT_RELU>(sm, O_X, XS, 128, O_T, TBS, aw2, ab2, HID);

    // ---- f-net layer 1: h1 = relu(x @ mw1^T + mb1) ----
    layer_fwd<COMP, ACT_RELU>(sm, O_H1, HS, 0, O_X, XS, mw1, mb1, CON);
    if (tid < TS * 3) {
        int s = tid / 3, w = tid - 3 * s;
        unsigned m = 0;
        for (int b = 0; b < 32; b++) {
            int idx = w * 32 + b;
            if (idx < COMP && sm[O_H1 + s * HS + idx] > 0.f) m |= 1u << b;
        }
        g_d1m[(sbase + s) * 3 + w] = m;
    }
    // ---- f-net layer 2 ----
    layer_fwd<COMP, ACT_RELU>(sm, O_H2, HS, 0, O_H1, HS, mw2, mb2, COMP);
    if (tid < TS * 3) {
        int s = tid / 3, w = tid - 3 * s;
        unsigned m = 0;
        for (int b = 0; b < 32; b++) {
            int idx = w * 32 + b;
            if (idx < COMP && sm[O_H2 + s * HS + idx] > 0.f) m |= 1u << b;
        }
        g_d2m[(sbase + s) * 3 + w] = m;
    }
    // ---- f-net layer 3 -> f_out (overwrites h1 region) ----
    layer_fwd<COMP, ACT_RELU>(sm, O_H1, HS, 0, O_H2, HS, mw3, mb3, COMP);
    for (int i = tid; i < TS * COMP; i += 256) {
        int s = i / COMP, o = i - s * COMP;
        g_fout[(sbase + s) * COMP + o] = sm[O_H1 + s * HS + o];
    }
    // ---- k-net ----
    layer_fwd<KS, ACT_TANH>(sm, O_K1, 33, 0, O_X, XS, kw1, kb1, CON);
    layer_fwd<16, ACT_TANH>(sm, O_K2, 17, 0, O_K1, 33, kw2, kb2, KS);
    if (tid < TS) {
        float z = kb3[0];
        #pragma unroll
        for (int i = 0; i < 16; i++) z = fmaf(sm[O_K2 + tid * 17 + i], kw3[i], z);
        g_kout[sbase + tid] = (z > 20.f) ? z : log1pf(expf(z));
    }
}

// =========================================================================
// Kernel 3: Jacobian norm + final output.
//   ||J||^2 = tr(Bm G Bm^T),  Bm = D3 W3 D2 W2 D1, G = W1 W1^T.
//   Fully compacted over active indices (d1/d2/d3 masks).
// =========================================================================
#define SPC 8   // samples per CTA (sequential)

// smem layout (float offsets), stride 88 everywhere
#define J_SW2  0
#define J_SW3  7480
#define J_SG   14960
#define J_CW3  22440
#define J_CW2  29920
#define J_CG   37400
#define J_CB   44880
#define J_FROW 52360
#define J_A1   52448
#define J_A2   52536
#define J_A3   52624
#define J_CNT  52712
#define J_WSUM 52720
#define J_SCAL 52728
#define JAC_SMEM_FLOATS 52736
#define JAC_SMEM_BYTES  (JAC_SMEM_FLOATS * 4)

__global__ __launch_bounds__(256)
void jac_kernel(const float* __restrict__ mw2, const float* __restrict__ mw3,
                float* __restrict__ out)
{
    extern __shared__ float sm[];
    const int tid = threadIdx.x;
    int* act1 = (int*)(sm + J_A1);
    int* act2 = (int*)(sm + J_A2);
    int* act3 = (int*)(sm + J_A3);
    int* cnt  = (int*)(sm + J_CNT);
    float* frow = sm + J_FROW;

    // stage W2, W3, G dense (stride 88)
    for (int i = tid; i < COMP * COMP; i += 256) {
        int r = i / COMP, c = i - r * COMP;
        sm[J_SW2 + r * 88 + c] = mw2[i];
        sm[J_SW3 + r * 88 + c] = mw3[i];
        sm[J_SG  + r * 88 + c] = g_G[i];
    }
    __syncthreads();

    for (int ss = 0; ss < SPC; ss++) {
        int gs = blockIdx.x * SPC + ss;

        if (tid < COMP) frow[tid] = g_fout[gs * COMP + tid];
        __syncthreads();

        // build compacted index lists (warp 0)
        if (tid < 32) {
            int lane = tid;
            for (int L = 0; L < 3; L++) {
                int base = 0;
                int* act = (L == 0) ? act1 : ((L == 1) ? act2 : act3);
                for (int w = 0; w < 3; w++) {
                    unsigned word;
                    if (L == 0)      word = g_d1m[gs * 3 + w];
                    else if (L == 1) word = g_d2m[gs * 3 + w];
                    else {
                        int idx = w * 32 + lane;
                        int fl = (idx < COMP) && (frow[idx] > 0.f);
                        word = __ballot_sync(0xFFFFFFFFu, fl);
                    }
                    int idx = w * 32 + lane;
                    if ((word >> lane) & 1u) {
                        int pos = base + __popc(word & ((1u << lane) - 1u));
                        act[pos] = idx;
                    }
                    base += __popc(word);
                }
                if (lane == 0) cnt[L] = base;
            }
        }
        __syncthreads();
        const int n1 = cnt[0], n2 = cnt[1], n3 = cnt[2];

        // gather compacted operands
        for (int e = tid; e < n3 * n2; e += 256) {
            int ii = e / n2, mm = e - ii * n2;
            sm[J_CW3 + ii * 88 + mm] = sm[J_SW3 + act3[ii] * 88 + act2[mm]];
        }
        for (int e = tid; e < n2 * n1; e += 256) {
            int mm = e / n1, jj = e - mm * n1;
            sm[J_CW2 + mm * 88 + jj] = sm[J_SW2 + act2[mm] * 88 + act1[jj]];
        }
        for (int e = tid; e < n1 * n1; e += 256) {
            int a = e / n1, b = e - a * n1;
            sm[J_CG + a * 88 + b] = sm[J_SG + act1[a] * 88 + act1[b]];
        }
        __syncthreads();

        // Bc[n3 x n1] = W3c @ W2c  (K = n2)
        for (int e = tid; e < n3 * n1; e += 256) {
            int ii = e / n1, jj = e - ii * n1;
            float acc = 0.f;
            const float* w3r = sm + J_CW3 + ii * 88;
            const float* w2c = sm + J_CW2 + jj;
            for (int kk = 0; kk < n2; kk++)
                acc = fmaf(w3r[kk], w2c[kk * 88], acc);
            sm[J_CB + ii * 88 + jj] = acc;
        }
        __syncthreads();

        // trace = sum_{ii,jj} (Bc Gc)[ii,jj] * Bc[ii,jj]
        float local = 0.f;
        for (int e = tid; e < n3 * n1; e += 256) {
            int ii = e / n1, jj = e - ii * n1;
            float t = 0.f;
            const float* br = sm + J_CB + ii * 88;
            const float* gc = sm + J_CG + jj;
            for (int kk = 0; kk < n1; kk++)
                t = fmaf(br[kk], gc[kk * 88], t);
            local = fmaf(t, sm[J_CB + ii * 88 + jj], local);
        }
        #pragma unroll
        for (int off = 16; off; off >>= 1)
            local += __shfl_down_sync(0xFFFFFFFFu, local, off);
        if ((tid & 31) == 0) sm[J_WSUM + (tid >> 5)] = local;
        __syncthreads();
        if (tid == 0) {
            float ns = 0.f;
            for (int w = 0; w < 8; w++) ns += sm[J_WSUM + w];
            sm[J_SCAL] = 1.f / (sqrtf(ns) + 1e-4f);
        }
        __syncthreads();

        if (tid < COMP) {
            float kv = g_kout[gs];
            out[gs * COMP + tid] = tanhf(kv * frow[tid] * sm[J_SCAL]);
        }
        __syncthreads();  // protect frow/cnt reuse next sample
    }
}

// =========================================================================
// launch
// =========================================================================
extern "C" void kernel_launch(void* const* d_in, const int* in_sizes, int n_in,
                              void* d_out, int out_size)
{
    const float* obs    = (const float*)d_in[0];
    const float* action = (const float*)d_in[1];
    const float* ow1 = (const float*)d_in[2];
    const float* ob1 = (const float*)d_in[3];
    const float* ow2 = (const float*)d_in[4];
    const float* ob2 = (const float*)d_in[5];
    const float* aw1 = (const float*)d_in[6];
    const float* ab1 = (const float*)d_in[7];
    const float* aw2 = (const float*)d_in[8];
    const float* ab2 = (const float*)d_in[9];
    const float* mw1 = (const float*)d_in[10];
    const float* mb1 = (const float*)d_in[11];
    const float* mw2 = (const float*)d_in[12];
    const float* mb2 = (const float*)d_in[13];
    const float* mw3 = (const float*)d_in[14];
    const float* mb3 = (const float*)d_in[15];
    const float* kw1 = (const float*)d_in[16];
    const float* kb1 = (const float*)d_in[17];
    const float* kw2 = (const float*)d_in[18];
    const float* kb2 = (const float*)d_in[19];
    const float* kw3 = (const float*)d_in[20];
    const float* kb3 = (const float*)d_in[21];
    float* out = (float*)d_out;

    cudaFuncSetAttribute(fwd_kernel, cudaFuncAttributeMaxDynamicSharedMemorySize,
                         FWD_SMEM_BYTES);
    cudaFuncSetAttribute(jac_kernel, cudaFuncAttributeMaxDynamicSharedMemorySize,
                         JAC_SMEM_BYTES);

    g_kernel<<<(COMP * COMP + 255) / 256, 256>>>(mw1);
    fwd_kernel<<<BATCH / TS, 256, FWD_SMEM_BYTES>>>(
        obs, action, ow1, ob1, ow2, ob2, aw1, ab1, aw2, ab2,
        mw1, mb1, mw2, mb2, mw3, mb3, kw1, kb1, kw2, kb2, kw3, kb3);
    jac_kernel<<<BATCH / SPC, 256, JAC_SMEM_BYTES>>>(mw2, mw3, out);
}

// round 2
// speedup vs baseline: 1.7271x; 1.7271x over previous
#include <cuda_runtime.h>
#include <math.h>

// Problem dims
#define BATCH 8192
#define OBS 64
#define ACT 16
#define HID 128
#define CON 256
#define COMP 85
#define KS 32

// ---------------- scratch (device globals; no allocation) ----------------
__device__ float g_G[COMP * COMP];          // W1 W1^T
__device__ float g_fout[BATCH * COMP];      // f-net output (relu(p3))
__device__ float g_kout[BATCH];             // k-net output (softplus)
__device__ unsigned g_d1m[BATCH * 3];       // d1 bitmask (85 bits in 3 words)
__device__ unsigned g_d2m[BATCH * 3];       // d2 bitmask

// =========================================================================
// Kernel 1: G = mw1 @ mw1^T   (85x85, K=256). One warp per output element.
// =========================================================================
__global__ __launch_bounds__(256)
void g_kernel(const float* __restrict__ mw1) {
    int gw = (blockIdx.x * 256 + threadIdx.x) >> 5;   // global warp id
    int lane = threadIdx.x & 31;
    if (gw >= COMP * COMP) return;
    int i = gw / COMP;
    int j = gw - i * COMP;
    const float4* a = (const float4*)(mw1 + i * CON);
    const float4* b = (const float4*)(mw1 + j * CON);
    float acc = 0.f;
    #pragma unroll
    for (int t = 0; t < 2; t++) {
        float4 av = a[lane + 32 * t];
        float4 bv = b[lane + 32 * t];
        acc += av.x * bv.x + av.y * bv.y + av.z * bv.z + av.w * bv.w;
    }
    #pragma unroll
    for (int off = 16; off; off >>= 1)
        acc += __shfl_down_sync(0xFFFFFFFFu, acc, off);
    if (lane == 0) g_G[gw] = acc;
}

// =========================================================================
// Kernel 2: fused forward pass. 64 samples per CTA, 256 threads.
// Thread map: sp = tid>>4 owns samples {4sp..4sp+3}; q = tid&15 owns
// output cols o = q + 16j.
// =========================================================================
#define TS 64

// smem layout (float offsets)
#define O_X   0            // x buffer 64 x 257 (concat of/af)
#define XS    257
#define O_W   16448        // weight staging 16512 floats
#define O_T   32960        // head layer-1 temp 64 x 129
#define TBS   129
#define O_IN  41216        // input staging 64 x 65 (also k1/k2 bufs)
#define O_K1  41216        // k1: 64 x 33
#define O_K2  43328        // k2: 64 x 17
#define O_H1  45376        // h1 / f_out: 64 x 87
#define O_H2  50944        // h2: 64 x 87
#define HS    87
#define FWD_SMEM_FLOATS 56512
#define FWD_SMEM_BYTES  (FWD_SMEM_FLOATS * 4)

#define ACT_RELU 0
#define ACT_TANH 1

template<int N, int ACTT>
__device__ __forceinline__ void layer_fwd(
    float* __restrict__ sm,
    int o_out, int outStride, int outColOff,
    int o_in, int inStride,
    const float* __restrict__ Wg, const float* __restrict__ bg, int K)
{
    constexpr int NJ = (N + 15) / 16;
    const int tid = threadIdx.x;
    const int sp = tid >> 4;       // 0..15, samples 4sp..4sp+3
    const int q = tid & 15;        // output col group

    float acc[4][NJ];
    #pragma unroll
    for (int s = 0; s < 4; s++)
        #pragma unroll
        for (int j = 0; j < NJ; j++) acc[s][j] = 0.f;

    float* wbuf = sm + O_W;

    for (int k0 = 0; k0 < K; k0 += 128) {
        int KC = K - k0; if (KC > 128) KC = 128;
        int WS = KC | 1;   // odd stride -> conflict-free weight columns
        __syncthreads();
        for (int i = tid; i < N * KC; i += 256) {
            int r = i / KC;
            int c = i - r * KC;
            wbuf[r * WS + c] = Wg[r * K + k0 + c];
        }
        __syncthreads();
        const float* in0 = sm + o_in + (4 * sp + 0) * inStride + k0;
        const float* in1 = sm + o_in + (4 * sp + 1) * inStride + k0;
        const float* in2 = sm + o_in + (4 * sp + 2) * inStride + k0;
        const float* in3 = sm + o_in + (4 * sp + 3) * inStride + k0;
        #pragma unroll 2
        for (int k = 0; k < KC; k++) {
            float a0 = in0[k], a1 = in1[k], a2 = in2[k], a3 = in3[k];
            const float* wr = wbuf + k + q * WS;
            #pragma unroll
            for (int j = 0; j < NJ; j++) {
                float w = wr[(j << 4) * WS];
                acc[0][j] = fmaf(a0, w, acc[0][j]);
                acc[1][j] = fmaf(a1, w, acc[1][j]);
                acc[2][j] = fmaf(a2, w, acc[2][j]);
                acc[3][j] = fmaf(a3, w, acc[3][j]);
            }
        }
    }
    #pragma unroll
    for (int j = 0; j < NJ; j++) {
        int o = q + (j << 4);
        if (o < N) {
            float bv = bg[o];
            #pragma unroll
            for (int s = 0; s < 4; s++) {
                float v = acc[s][j] + bv;
                if (ACTT == ACT_RELU) v = fmaxf(v, 0.f);
                else if (ACTT == ACT_TANH) v = tanhf(v);
                sm[o_out + (4 * sp + s) * outStride + outColOff + o] = v;
            }
        }
    }
    __syncthreads();
}

__global__ __launch_bounds__(256)
void fwd_kernel(
    const float* __restrict__ obs, const float* __restrict__ action,
    const float* __restrict__ ow1, const float* __restrict__ ob1,
    const float* __restrict__ ow2, const float* __restrict__ ob2,
    const float* __restrict__ aw1, const float* __restrict__ ab1,
    const float* __restrict__ aw2, const float* __restrict__ ab2,
    const float* __restrict__ mw1, const float* __restrict__ mb1,
    const float* __restrict__ mw2, const float* __restrict__ mb2,
    const float* __restrict__ mw3, const float* __restrict__ mb3,
    const float* __restrict__ kw1, const float* __restrict__ kb1,
    const float* __restrict__ kw2, const float* __restrict__ kb2,
    const float* __restrict__ kw3, const float* __restrict__ kb3)
{
    extern __shared__ float sm[];
    const int tid = threadIdx.x;
    const int sbase = blockIdx.x * TS;

    // ---- obs head ----
    for (int i = tid; i < TS * OBS; i += 256) {
        int s = i >> 6, k = i & 63;
        sm[O_IN + s * 65 + k] = obs[(sbase + s) * OBS + k];
    }
    __syncthreads();
    layer_fwd<HID, ACT_RELU>(sm, O_T, TBS, 0, O_IN, 65, ow1, ob1, OBS);
    layer_fwd<HID, ACT_RELU>(sm, O_X, XS, 0, O_T, TBS, ow2, ob2, HID);

    // ---- action head ----
    for (int i = tid; i < TS * ACT; i += 256) {
        int s = i >> 4, k = i & 15;
        sm[O_IN + s * 17 + k] = action[(sbase + s) * ACT + k];
    }
    __syncthreads();
    layer_fwd<HID, ACT_RELU>(sm, O_T, TBS, 0, O_IN, 17, aw1, ab1, ACT);
    layer_fwd<HID, ACT_RELU>(sm, O_X, XS, 128, O_T, TBS, aw2, ab2, HID);

    // ---- f-net layer 1: h1 = relu(x @ mw1^T + mb1) ----
    layer_fwd<COMP, ACT_RELU>(sm, O_H1, HS, 0, O_X, XS, mw1, mb1, CON);
    if (tid < TS * 3) {
        int s = tid / 3, w = tid - 3 * s;
        unsigned m = 0;
        for (int b = 0; b < 32; b++) {
            int idx = w * 32 + b;
            if (idx < COMP && sm[O_H1 + s * HS + idx] > 0.f) m |= 1u << b;
        }
        g_d1m[(sbase + s) * 3 + w] = m;
    }
    // ---- f-net layer 2 ----
    layer_fwd<COMP, ACT_RELU>(sm, O_H2, HS, 0, O_H1, HS, mw2, mb2, COMP);
    if (tid < TS * 3) {
        int s = tid / 3, w = tid - 3 * s;
        unsigned m = 0;
        for (int b = 0; b < 32; b++) {
            int idx = w * 32 + b;
            if (idx < COMP && sm[O_H2 + s * HS + idx] > 0.f) m |= 1u << b;
        }
        g_d2m[(sbase + s) * 3 + w] = m;
    }
    // ---- f-net layer 3 -> f_out (overwrites h1 region) ----
    layer_fwd<COMP, ACT_RELU>(sm, O_H1, HS, 0, O_H2, HS, mw3, mb3, COMP);
    for (int i = tid; i < TS * COMP; i += 256) {
        int s = i / COMP, o = i - s * COMP;
        g_fout[(sbase + s) * COMP + o] = sm[O_H1 + s * HS + o];
    }
    // ---- k-net ----
    layer_fwd<KS, ACT_TANH>(sm, O_K1, 33, 0, O_X, XS, kw1, kb1, CON);
    layer_fwd<16, ACT_TANH>(sm, O_K2, 17, 0, O_K1, 33, kw2, kb2, KS);
    if (tid < TS) {
        float z = kb3[0];
        #pragma unroll
        for (int i = 0; i < 16; i++) z = fmaf(sm[O_K2 + tid * 17 + i], kw3[i], z);
        g_kout[sbase + tid] = (z > 20.f) ? z : log1pf(expf(z));
    }
}

// =========================================================================
// Kernel 3: Jacobian norm + final output.
//   ||J||^2 = tr(Bm G Bm^T),  Bm = D3 W3 D2 W2 D1, G = W1 W1^T.
//   Fully compacted over active indices; 4x4 register tiling.
// =========================================================================
#define SPC 8   // samples per CTA (sequential)

// smem layout (float offsets)
#define J_SW2  0                 // 85 x 88
#define J_SW3  7480              // 85 x 88
#define J_SG   14960             // 85 x 88
#define J_CW3  22440             // 88 rows x stride 92 (row-broadcast reads)
#define J_CW2  30536             // 85 rows x stride 88 (float4 row reads)
#define J_CG   38016             // 88 rows x stride 88 (float4 row reads)
#define J_CB   45760             // 88 rows x stride 92 (row-broadcast reads)
#define J_FROW 53856             // 88
#define J_A1   53944             // 88 ints
#define J_A2   54032
#define J_A3   54120
#define J_CNT  54208             // 4
#define J_WSUM 54216             // 8
#define J_SCAL 54224
#define JAC_SMEM_FLOATS 54240
#define JAC_SMEM_BYTES  (JAC_SMEM_FLOATS * 4)

__global__ __launch_bounds__(256)
void jac_kernel(const float* __restrict__ mw2, const float* __restrict__ mw3,
                float* __restrict__ out)
{
    extern __shared__ float sm[];
    const int tid = threadIdx.x;
    int* act1 = (int*)(sm + J_A1);
    int* act2 = (int*)(sm + J_A2);
    int* act3 = (int*)(sm + J_A3);
    int* cnt  = (int*)(sm + J_CNT);
    float* frow = sm + J_FROW;

    // stage W2, W3, G dense (stride 88)
    for (int i = tid; i < COMP * COMP; i += 256) {
        int r = i / COMP, c = i - r * COMP;
        sm[J_SW2 + r * 88 + c] = mw2[i];
        sm[J_SW3 + r * 88 + c] = mw3[i];
        sm[J_SG  + r * 88 + c] = g_G[i];
    }
    __syncthreads();

    for (int ss = 0; ss < SPC; ss++) {
        int gs = blockIdx.x * SPC + ss;

        if (tid < COMP) frow[tid] = g_fout[gs * COMP + tid];
        __syncthreads();

        // build compacted index lists (warp 0)
        if (tid < 32) {
            int lane = tid;
            for (int L = 0; L < 3; L++) {
                int base = 0;
                int* act = (L == 0) ? act1 : ((L == 1) ? act2 : act3);
                for (int w = 0; w < 3; w++) {
                    unsigned word;
                    if (L == 0)      word = g_d1m[gs * 3 + w];
                    else if (L == 1) word = g_d2m[gs * 3 + w];
                    else {
                        int idx = w * 32 + lane;
                        int fl = (idx < COMP) && (frow[idx] > 0.f);
                        word = __ballot_sync(0xFFFFFFFFu, fl);
                    }
                    int idx = w * 32 + lane;
                    if ((word >> lane) & 1u) {
                        int pos = base + __popc(word & ((1u << lane) - 1u));
                        act[pos] = idx;
                    }
                    base += __popc(word);
                }
                if (lane == 0) cnt[L] = base;
            }
        }
        __syncthreads();
        const int n1 = cnt[0], n2 = cnt[1], n3 = cnt[2];
        const int n1p = (n1 + 3) & ~3;
        const int n3p = (n3 + 3) & ~3;

        // gather compacted operands (zero-padded to multiples of 4)
        for (int e = tid; e < n3p * n2; e += 256) {
            int ii = e / n2, mm = e - ii * n2;
            sm[J_CW3 + ii * 92 + mm] =
                (ii < n3) ? sm[J_SW3 + act3[ii] * 88 + act2[mm]] : 0.f;
        }
        for (int e = tid; e < n2 * n1p; e += 256) {
            int mm = e / n1p, jj = e - mm * n1p;
            sm[J_CW2 + mm * 88 + jj] =
                (jj < n1) ? sm[J_SW2 + act2[mm] * 88 + act1[jj]] : 0.f;
        }
        for (int e = tid; e < n1 * n1p; e += 256) {
            int a = e / n1p, b = e - a * n1p;
            sm[J_CG + a * 88 + b] =
                (b < n1) ? sm[J_SG + act1[a] * 88 + act1[b]] : 0.f;
        }
        __syncthreads();

        const int nb1 = n1p >> 2, nb3 = n3p >> 2;
        const int ntiles = nb3 * nb1;

        // Bc[n3p x n1p] = W3c @ W2c  (K = n2), 4x4 register tiles
        for (int t = tid; t < ntiles; t += 256) {
            int bi = t / nb1, bj = t - bi * nb1;
            int ii = bi << 2, jj = bj << 2;
            float acc00=0,acc01=0,acc02=0,acc03=0;
            float acc10=0,acc11=0,acc12=0,acc13=0;
            float acc20=0,acc21=0,acc22=0,acc23=0;
            float acc30=0,acc31=0,acc32=0,acc33=0;
            const float* w3 = sm + J_CW3 + ii * 92;
            const float* w2 = sm + J_CW2 + jj;
            #pragma unroll 2
            for (int kk = 0; kk < n2; kk++) {
                float a0 = w3[kk];
                float a1 = w3[92 + kk];
                float a2 = w3[184 + kk];
                float a3 = w3[276 + kk];
                float4 b = *(const float4*)(w2 + kk * 88);
                acc00 = fmaf(a0, b.x, acc00); acc01 = fmaf(a0, b.y, acc01);
                acc02 = fmaf(a0, b.z, acc02); acc03 = fmaf(a0, b.w, acc03);
                acc10 = fmaf(a1, b.x, acc10); acc11 = fmaf(a1, b.y, acc11);
                acc12 = fmaf(a1, b.z, acc12); acc13 = fmaf(a1, b.w, acc13);
                acc20 = fmaf(a2, b.x, acc20); acc21 = fmaf(a2, b.y, acc21);
                acc22 = fmaf(a2, b.z, acc22); acc23 = fmaf(a2, b.w, acc23);
                acc30 = fmaf(a3, b.x, acc30); acc31 = fmaf(a3, b.y, acc31);
                acc32 = fmaf(a3, b.z, acc32); acc33 = fmaf(a3, b.w, acc33);
            }
            float* cb = sm + J_CB + ii * 92 + jj;
            *(float4*)(cb)       = make_float4(acc00, acc01, acc02, acc03);
            *(float4*)(cb + 92)  = make_float4(acc10, acc11, acc12, acc13);
            *(float4*)(cb + 184) = make_float4(acc20, acc21, acc22, acc23);
            *(float4*)(cb + 276) = make_float4(acc30, acc31, acc32, acc33);
        }
        __syncthreads();

        // trace = sum (Bc Gc) o Bc, 4x4 register tiles
        float local = 0.f;
        for (int t = tid; t < ntiles; t += 256) {
            int bi = t / nb1, bj = t - bi * nb1;
            int ii = bi << 2, jj = bj << 2;
            const float* cb = sm + J_CB + ii * 92;
            const float* g = sm + J_CG + jj;
            float acc00=0,acc01=0,acc02=0,acc03=0;
            float acc10=0,acc11=0,acc12=0,acc13=0;
            float acc20=0,acc21=0,acc22=0,acc23=0;
            float acc30=0,acc31=0,acc32=0,acc33=0;
            #pragma unroll 2
            for (int kk = 0; kk < n1; kk++) {
                float a0 = cb[kk];
                float a1 = cb[92 + kk];
                float a2 = cb[184 + kk];
                float a3 = cb[276 + kk];
                float4 b = *(const float4*)(g + kk * 88);
                acc00 = fmaf(a0, b.x, acc00); acc01 = fmaf(a0, b.y, acc01);
                acc02 = fmaf(a0, b.z, acc02); acc03 = fmaf(a0, b.w, acc03);
                acc10 = fmaf(a1, b.x, acc10); acc11 = fmaf(a1, b.y, acc11);
                acc12 = fmaf(a1, b.z, acc12); acc13 = fmaf(a1, b.w, acc13);
                acc20 = fmaf(a2, b.x, acc20); acc21 = fmaf(a2, b.y, acc21);
                acc22 = fmaf(a2, b.z, acc22); acc23 = fmaf(a2, b.w, acc23);
                acc30 = fmaf(a3, b.x, acc30); acc31 = fmaf(a3, b.y, acc31);
                acc32 = fmaf(a3, b.z, acc32); acc33 = fmaf(a3, b.w, acc33);
            }
            const float* cbt = sm + J_CB + ii * 92 + jj;
            float4 c0 = *(const float4*)(cbt);
            float4 c1 = *(const float4*)(cbt + 92);
            float4 c2 = *(const float4*)(cbt + 184);
            float4 c3 = *(const float4*)(cbt + 276);
            local += acc00*c0.x + acc01*c0.y + acc02*c0.z + acc03*c0.w
                   + acc10*c1.x + acc11*c1.y + acc12*c1.z + acc13*c1.w
                   + acc20*c2.x + acc21*c2.y + acc22*c2.z + acc23*c2.w
                   + acc30*c3.x + acc31*c3.y + acc32*c3.z + acc33*c3.w;
        }
        #pragma unroll
        for (int off = 16; off; off >>= 1)
            local += __shfl_down_sync(0xFFFFFFFFu, local, off);
        if ((tid & 31) == 0) sm[J_WSUM + (tid >> 5)] = local;
        __syncthreads();
        if (tid == 0) {
            float ns = 0.f;
            for (int w = 0; w < 8; w++) ns += sm[J_WSUM + w];
            sm[J_SCAL] = 1.f / (sqrtf(ns) + 1e-4f);
        }
        __syncthreads();

        if (tid < COMP) {
            float kv = g_kout[gs];
            out[gs * COMP + tid] = tanhf(kv * frow[tid] * sm[J_SCAL]);
        }
        __syncthreads();  // protect frow/cnt reuse next sample
    }
}

// =========================================================================
// launch
// =========================================================================
extern "C" void kernel_launch(void* const* d_in, const int* in_sizes, int n_in,
                              void* d_out, int out_size)
{
    const float* obs    = (const float*)d_in[0];
    const float* action = (const float*)d_in[1];
    const float* ow1 = (const float*)d_in[2];
    const float* ob1 = (const float*)d_in[3];
    const float* ow2 = (const float*)d_in[4];
    const float* ob2 = (const float*)d_in[5];
    const float* aw1 = (const float*)d_in[6];
    const float* ab1 = (const float*)d_in[7];
    const float* aw2 = (const float*)d_in[8];
    const float* ab2 = (const float*)d_in[9];
    const float* mw1 = (const float*)d_in[10];
    const float* mb1 = (const float*)d_in[11];
    const float* mw2 = (const float*)d_in[12];
    const float* mb2 = (const float*)d_in[13];
    const float* mw3 = (const float*)d_in[14];
    const float* mb3 = (const float*)d_in[15];
    const float* kw1 = (const float*)d_in[16];
    const float* kb1 = (const float*)d_in[17];
    const float* kw2 = (const float*)d_in[18];
    const float* kb2 = (const float*)d_in[19];
    const float* kw3 = (const float*)d_in[20];
    const float* kb3 = (const float*)d_in[21];
    float* out = (float*)d_out;

    cudaFuncSetAttribute(fwd_kernel, cudaFuncAttributeMaxDynamicSharedMemorySize,
                         FWD_SMEM_BYTES);
    cudaFuncSetAttribute(jac_kernel, cudaFuncAttributeMaxDynamicSharedMemorySize,
                         JAC_SMEM_BYTES);

    g_kernel<<<(COMP * COMP * 32 + 255) / 256, 256>>>(mw1);
    fwd_kernel<<<BATCH / TS, 256, FWD_SMEM_BYTES>>>(
        obs, action, ow1, ob1, ow2, ob2, aw1, ab1, aw2, ab2,
        mw1, mb1, mw2, mb2, mw3, mb3, kw1, kb1, kw2, kb2, kw3, kb3);
    jac_kernel<<<BATCH / SPC, 256, JAC_SMEM_BYTES>>>(mw2, mw3, out);
}

// round 3
// speedup vs baseline: 2.1441x; 1.2415x over previous
#include <cuda_runtime.h>
#include <math.h>

// Problem dims
#define BATCH 8192
#define OBS 64
#define ACT 16
#define HID 128
#define CON 256
#define COMP 85
#define KS 32

// ---------------- scratch (device globals; no allocation) ----------------
__device__ float g_G[COMP * COMP];          // W1 W1^T
__device__ float g_fout[BATCH * COMP];      // f-net output (relu(p3))
__device__ float g_kout[BATCH];             // k-net output (softplus)
__device__ unsigned g_d1m[BATCH * 3];       // d1 bitmask (85 bits in 3 words)
__device__ unsigned g_d2m[BATCH * 3];       // d2 bitmask

// =========================================================================
// Kernel 1: G = mw1 @ mw1^T   (85x85, K=256). One warp per output element.
// =========================================================================
__global__ __launch_bounds__(256)
void g_kernel(const float* __restrict__ mw1) {
    int gw = (blockIdx.x * 256 + threadIdx.x) >> 5;   // global warp id
    int lane = threadIdx.x & 31;
    if (gw >= COMP * COMP) return;
    int i = gw / COMP;
    int j = gw - i * COMP;
    const float4* a = (const float4*)(mw1 + i * CON);
    const float4* b = (const float4*)(mw1 + j * CON);
    float acc = 0.f;
    #pragma unroll
    for (int t = 0; t < 2; t++) {
        float4 av = a[lane + 32 * t];
        float4 bv = b[lane + 32 * t];
        acc += av.x * bv.x + av.y * bv.y + av.z * bv.z + av.w * bv.w;
    }
    #pragma unroll
    for (int off = 16; off; off >>= 1)
        acc += __shfl_down_sync(0xFFFFFFFFu, acc, off);
    if (lane == 0) g_G[gw] = acc;
}

// =========================================================================
// Kernel 2: fused forward pass. 64 samples per CTA, 512 threads.
// Thread map: sp = tid>>5 owns samples {4sp..4sp+3}; q = tid&31 owns
// output cols o = q + 32j.  All lanes of a warp share sp -> activation
// LDS are pure broadcasts; weight LDS conflict-free (odd stride).
// =========================================================================
#define TS 64
#define FWD_THREADS 512

// smem layout (float offsets)
#define O_X   0            // x buffer 64 x 257 (concat of/af)
#define XS    257
#define O_W   16448        // weight staging 16512 floats
#define O_T   32960        // head layer-1 temp 64 x 129
#define TBS   129
#define O_IN  41216        // input staging 64 x 65 (also k1/k2 bufs)
#define O_K1  41216        // k1: 64 x 33
#define O_K2  43328        // k2: 64 x 17
#define O_H1  45376        // h1 / f_out: 64 x 87
#define O_H2  50944        // h2: 64 x 87
#define HS    87
#define FWD_SMEM_FLOATS 56512
#define FWD_SMEM_BYTES  (FWD_SMEM_FLOATS * 4)

#define ACT_RELU 0
#define ACT_TANH 1

template<int N, int ACTT>
__device__ __forceinline__ void layer_fwd(
    float* __restrict__ sm,
    int o_out, int outStride, int outColOff,
    int o_in, int inStride,
    const float* __restrict__ Wg, const float* __restrict__ bg, int K)
{
    constexpr int NJ = (N + 31) / 32;
    const int tid = threadIdx.x;
    const int sp = tid >> 5;       // 0..15, samples 4sp..4sp+3
    const int q = tid & 31;        // output col group

    float acc[4][NJ];
    #pragma unroll
    for (int s = 0; s < 4; s++)
        #pragma unroll
        for (int j = 0; j < NJ; j++) acc[s][j] = 0.f;

    float* wbuf = sm + O_W;

    for (int k0 = 0; k0 < K; k0 += 128) {
        int KC = K - k0; if (KC > 128) KC = 128;
        int WS = KC | 1;   // odd stride -> conflict-free weight columns
        __syncthreads();
        for (int i = tid; i < N * KC; i += FWD_THREADS) {
            int r = i / KC;
            int c = i - r * KC;
            wbuf[r * WS + c] = Wg[r * K + k0 + c];
        }
        __syncthreads();
        const float* in0 = sm + o_in + (4 * sp + 0) * inStride + k0;
        const float* in1 = sm + o_in + (4 * sp + 1) * inStride + k0;
        const float* in2 = sm + o_in + (4 * sp + 2) * inStride + k0;
        const float* in3 = sm + o_in + (4 * sp + 3) * inStride + k0;
        #pragma unroll 2
        for (int k = 0; k < KC; k++) {
            float a0 = in0[k], a1 = in1[k], a2 = in2[k], a3 = in3[k];
            const float* wr = wbuf + k + q * WS;
            #pragma unroll
            for (int j = 0; j < NJ; j++) {
                float w = wr[(j << 5) * WS];
                acc[0][j] = fmaf(a0, w, acc[0][j]);
                acc[1][j] = fmaf(a1, w, acc[1][j]);
                acc[2][j] = fmaf(a2, w, acc[2][j]);
                acc[3][j] = fmaf(a3, w, acc[3][j]);
            }
        }
    }
    #pragma unroll
    for (int j = 0; j < NJ; j++) {
        int o = q + (j << 5);
        if (o < N) {
            float bv = bg[o];
            #pragma unroll
            for (int s = 0; s < 4; s++) {
                float v = acc[s][j] + bv;
                if (ACTT == ACT_RELU) v = fmaxf(v, 0.f);
                else if (ACTT == ACT_TANH) v = tanhf(v);
                sm[o_out + (4 * sp + s) * outStride + outColOff + o] = v;
            }
        }
    }
    __syncthreads();
}

__global__ __launch_bounds__(FWD_THREADS)
void fwd_kernel(
    const float* __restrict__ obs, const float* __restrict__ action,
    const float* __restrict__ ow1, const float* __restrict__ ob1,
    const float* __restrict__ ow2, const float* __restrict__ ob2,
    const float* __restrict__ aw1, const float* __restrict__ ab1,
    const float* __restrict__ aw2, const float* __restrict__ ab2,
    const float* __restrict__ mw1, const float* __restrict__ mb1,
    const float* __restrict__ mw2, const float* __restrict__ mb2,
    const float* __restrict__ mw3, const float* __restrict__ mb3,
    const float* __restrict__ kw1, const float* __restrict__ kb1,
    const float* __restrict__ kw2, const float* __restrict__ kb2,
    const float* __restrict__ kw3, const float* __restrict__ kb3)
{
    extern __shared__ float sm[];
    const int tid = threadIdx.x;
    const int sbase = blockIdx.x * TS;

    // ---- obs head ----
    for (int i = tid; i < TS * OBS; i += FWD_THREADS) {
        int s = i >> 6, k = i & 63;
        sm[O_IN + s * 65 + k] = obs[(sbase + s) * OBS + k];
    }
    __syncthreads();
    layer_fwd<HID, ACT_RELU>(sm, O_T, TBS, 0, O_IN, 65, ow1, ob1, OBS);
    layer_fwd<HID, ACT_RELU>(sm, O_X, XS, 0, O_T, TBS, ow2, ob2, HID);

    // ---- action head ----
    for (int i = tid; i < TS * ACT; i += FWD_THREADS) {
        int s = i >> 4, k = i & 15;
        sm[O_IN + s * 17 + k] = action[(sbase + s) * ACT + k];
    }
    __syncthreads();
    layer_fwd<HID, ACT_RELU>(sm, O_T, TBS, 0, O_IN, 17, aw1, ab1, ACT);
    layer_fwd<HID, ACT_RELU>(sm, O_X, XS, 128, O_T, TBS, aw2, ab2, HID);

    // ---- f-net layer 1: h1 = relu(x @ mw1^T + mb1) ----
    layer_fwd<COMP, ACT_RELU>(sm, O_H1, HS, 0, O_X, XS, mw1, mb1, CON);
    if (tid < TS * 3) {
        int s = tid / 3, w = tid - 3 * s;
        unsigned m = 0;
        for (int b = 0; b < 32; b++) {
            int idx = w * 32 + b;
            if (idx < COMP && sm[O_H1 + s * HS + idx] > 0.f) m |= 1u << b;
        }
        g_d1m[(sbase + s) * 3 + w] = m;
    }
    // ---- f-net layer 2 ----
    layer_fwd<COMP, ACT_RELU>(sm, O_H2, HS, 0, O_H1, HS, mw2, mb2, COMP);
    if (tid < TS * 3) {
        int s = tid / 3, w = tid - 3 * s;
        unsigned m = 0;
        for (int b = 0; b < 32; b++) {
            int idx = w * 32 + b;
            if (idx < COMP && sm[O_H2 + s * HS + idx] > 0.f) m |= 1u << b;
        }
        g_d2m[(sbase + s) * 3 + w] = m;
    }
    // ---- f-net layer 3 -> f_out (overwrites h1 region) ----
    layer_fwd<COMP, ACT_RELU>(sm, O_H1, HS, 0, O_H2, HS, mw3, mb3, COMP);
    for (int i = tid; i < TS * COMP; i += FWD_THREADS) {
        int s = i / COMP, o = i - s * COMP;
        g_fout[(sbase + s) * COMP + o] = sm[O_H1 + s * HS + o];
    }
    // ---- k-net ----
    layer_fwd<KS, ACT_TANH>(sm, O_K1, 33, 0, O_X, XS, kw1, kb1, CON);
    layer_fwd<16, ACT_TANH>(sm, O_K2, 17, 0, O_K1, 33, kw2, kb2, KS);
    if (tid < TS) {
        float z = kb3[0];
        #pragma unroll
        for (int i = 0; i < 16; i++) z = fmaf(sm[O_K2 + tid * 17 + i], kw3[i], z);
        g_kout[sbase + tid] = (z > 20.f) ? z : log1pf(expf(z));
    }
}

// =========================================================================
// Kernel 3: Jacobian norm + final output.
//   ||J||^2 = tr(Bm G Bm^T) = sum_{a,b} (Bc^T Bc)[a,b] * G[act1[a],act1[b]]
//   Bc = W3c @ W2c (compacted). No Gc buffer, no dense weight staging:
//   gathers read straight from global (L1-resident, 28KB each).
//   Smem ~92KB -> 2 CTAs/SM.
// =========================================================================
#define SPC 8   // samples per CTA (sequential)

// smem layout (float offsets), stride 88
#define J_CW3  0                 // 88 x 88
#define J_CW2  7744              // 88 x 88
#define J_CB   15488             // 88 x 88
#define J_FROW 23232             // 88
#define J_A1   23320             // 88 ints
#define J_A2   23408
#define J_A3   23496
#define J_CNT  23584             // 4
#define J_WSUM 23588             // 8
#define JAC_SMEM_FLOATS 23600
#define JAC_SMEM_BYTES  (JAC_SMEM_FLOATS * 4)

__global__ __launch_bounds__(256)
void jac_kernel(const float* __restrict__ mw2, const float* __restrict__ mw3,
                float* __restrict__ out)
{
    extern __shared__ float sm[];
    const int tid = threadIdx.x;
    int* act1 = (int*)(sm + J_A1);
    int* act2 = (int*)(sm + J_A2);
    int* act3 = (int*)(sm + J_A3);
    int* cnt  = (int*)(sm + J_CNT);
    float* frow = sm + J_FROW;

    for (int ss = 0; ss < SPC; ss++) {
        int gs = blockIdx.x * SPC + ss;

        if (tid < COMP) frow[tid] = g_fout[gs * COMP + tid];
        __syncthreads();

        // build compacted index lists: warp L handles level L (L=0,1,2)
        if (tid < 96) {
            int L = tid >> 5;
            int lane = tid & 31;
            int base = 0;
            int* act = (L == 0) ? act1 : ((L == 1) ? act2 : act3);
            for (int w = 0; w < 3; w++) {
                unsigned word;
                if (L == 0)      word = g_d1m[gs * 3 + w];
                else if (L == 1) word = g_d2m[gs * 3 + w];
                else {
                    int idx = w * 32 + lane;
                    int fl = (idx < COMP) && (frow[idx] > 0.f);
                    word = __ballot_sync(0xFFFFFFFFu, fl);
                }
                int idx = w * 32 + lane;
                if ((word >> lane) & 1u) {
                    int pos = base + __popc(word & ((1u << lane) - 1u));
                    act[pos] = idx;
                }
                base += __popc(word);
            }
            // zero-pad act1 so padded trace gathers stay in-bounds
            if (L == 0) {
                int np = (base + 3) & ~3;
                for (int p = base + lane; p < np; p += 32) act[p] = 0;
            }
            if (lane == 0) cnt[L] = base;
        }
        __syncthreads();
        const int n1 = cnt[0], n2 = cnt[1], n3 = cnt[2];
        const int n1p = (n1 + 3) & ~3;
        const int n3p = (n3 + 3) & ~3;

        // gather compacted W3, W2 from global (L1-resident after sample 0)
        for (int e = tid; e < n3p * n2; e += 256) {
            int ii = e / n2, mm = e - ii * n2;
            sm[J_CW3 + ii * 88 + mm] =
                (ii < n3) ? __ldg(mw3 + act3[ii] * COMP + act2[mm]) : 0.f;
        }
        for (int e = tid; e < n2 * n1p; e += 256) {
            int mm = e / n1p, jj = e - mm * n1p;
            sm[J_CW2 + mm * 88 + jj] =
                (jj < n1) ? __ldg(mw2 + act2[mm] * COMP + act1[jj]) : 0.f;
        }
        __syncthreads();

        const int nb1 = n1p >> 2, nb3 = n3p >> 2;

        // Bc[n3p x n1p] = W3c @ W2c  (K = n2), 4x4 register tiles
        for (int t = tid; t < nb3 * nb1; t += 256) {
            int bi = t / nb1, bj = t - bi * nb1;
            int ii = bi << 2, jj = bj << 2;
            float acc00=0,acc01=0,acc02=0,acc03=0;
            float acc10=0,acc11=0,acc12=0,acc13=0;
            float acc20=0,acc21=0,acc22=0,acc23=0;
            float acc30=0,acc31=0,acc32=0,acc33=0;
            const float* w3 = sm + J_CW3 + ii * 88;
            const float* w2 = sm + J_CW2 + jj;
            #pragma unroll 2
            for (int kk = 0; kk < n2; kk++) {
                float a0 = w3[kk];
                float a1 = w3[88 + kk];
                float a2 = w3[176 + kk];
                float a3 = w3[264 + kk];
                float4 b = *(const float4*)(w2 + kk * 88);
                acc00 = fmaf(a0, b.x, acc00); acc01 = fmaf(a0, b.y, acc01);
                acc02 = fmaf(a0, b.z, acc02); acc03 = fmaf(a0, b.w, acc03);
                acc10 = fmaf(a1, b.x, acc10); acc11 = fmaf(a1, b.y, acc11);
                acc12 = fmaf(a1, b.z, acc12); acc13 = fmaf(a1, b.w, acc13);
                acc20 = fmaf(a2, b.x, acc20); acc21 = fmaf(a2, b.y, acc21);
                acc22 = fmaf(a2, b.z, acc22); acc23 = fmaf(a2, b.w, acc23);
                acc30 = fmaf(a3, b.x, acc30); acc31 = fmaf(a3, b.y, acc31);
                acc32 = fmaf(a3, b.z, acc32); acc33 = fmaf(a3, b.w, acc33);
            }
            float* cb = sm + J_CB + ii * 88 + jj;
            *(float4*)(cb)       = make_float4(acc00, acc01, acc02, acc03);
            *(float4*)(cb + 88)  = make_float4(acc10, acc11, acc12, acc13);
            *(float4*)(cb + 176) = make_float4(acc20, acc21, acc22, acc23);
            *(float4*)(cb + 264) = make_float4(acc30, acc31, acc32, acc33);
        }
        __syncthreads();

        // trace = sum_{a,b} (Bc^T Bc)[a,b] * G[act1[a], act1[b]]
        // 4x4 (a,b) tiles, K = n3 rows of Bc; G gathered from global.
        float local = 0.f;
        for (int t = tid; t < nb1 * nb1; t += 256) {
            int bi = t / nb1, bj = t - bi * nb1;
            int aa = bi << 2, bb = bj << 2;
            const float* ca = sm + J_CB + aa;
            const float* cbp = sm + J_CB + bb;
            float s00=0,s01=0,s02=0,s03=0;
            float s10=0,s11=0,s12=0,s13=0;
            float s20=0,s21=0,s22=0,s23=0;
            float s30=0,s31=0,s32=0,s33=0;
            #pragma unroll 2
            for (int kk = 0; kk < n3; kk++) {
                float4 u = *(const float4*)(ca + kk * 88);
                float4 v = *(const float4*)(cbp + kk * 88);
                s00 = fmaf(u.x, v.x, s00); s01 = fmaf(u.x, v.y, s01);
                s02 = fmaf(u.x, v.z, s02); s03 = fmaf(u.x, v.w, s03);
                s10 = fmaf(u.y, v.x, s10); s11 = fmaf(u.y, v.y, s11);
                s12 = fmaf(u.y, v.z, s12); s13 = fmaf(u.y, v.w, s13);
                s20 = fmaf(u.z, v.x, s20); s21 = fmaf(u.z, v.y, s21);
                s22 = fmaf(u.z, v.z, s22); s23 = fmaf(u.z, v.w, s23);
                s30 = fmaf(u.w, v.x, s30); s31 = fmaf(u.w, v.y, s31);
                s32 = fmaf(u.w, v.z, s32); s33 = fmaf(u.w, v.w, s33);
            }
            int ra0 = act1[aa] * COMP, ra1 = act1[aa+1] * COMP;
            int ra2 = act1[aa+2] * COMP, ra3 = act1[aa+3] * COMP;
            int cb0 = act1[bb], cb1 = act1[bb+1], cb2 = act1[bb+2], cb3 = act1[bb+3];
            local = fmaf(s00, __ldg(g_G + ra0 + cb0), local);
            local = fmaf(s01, __ldg(g_G + ra0 + cb1), local);
            local = fmaf(s02, __ldg(g_G + ra0 + cb2), local);
            local = fmaf(s03, __ldg(g_G + ra0 + cb3), local);
            local = fmaf(s10, __ldg(g_G + ra1 + cb0), local);
            local = fmaf(s11, __ldg(g_G + ra1 + cb1), local);
            local = fmaf(s12, __ldg(g_G + ra1 + cb2), local);
            local = fmaf(s13, __ldg(g_G + ra1 + cb3), local);
            local = fmaf(s20, __ldg(g_G + ra2 + cb0), local);
            local = fmaf(s21, __ldg(g_G + ra2 + cb1), local);
            local = fmaf(s22, __ldg(g_G + ra2 + cb2), local);
            local = fmaf(s23, __ldg(g_G + ra2 + cb3), local);
            local = fmaf(s30, __ldg(g_G + ra3 + cb0), local);
            local = fmaf(s31, __ldg(g_G + ra3 + cb1), local);
            local = fmaf(s32, __ldg(g_G + ra3 + cb2), local);
            local = fmaf(s33, __ldg(g_G + ra3 + cb3), local);
        }
        #pragma unroll
        for (int off = 16; off; off >>= 1)
            local += __shfl_down_sync(0xFFFFFFFFu, local, off);
        if ((tid & 31) == 0) sm[J_WSUM + (tid >> 5)] = local;
        __syncthreads();

        if (tid < COMP) {
            float ns = 0.f;
            #pragma unroll
            for (int w = 0; w < 8; w++) ns += sm[J_WSUM + w];
            float scal = 1.f / (sqrtf(ns) + 1e-4f);
            float kv = g_kout[gs];
            out[gs * COMP + tid] = tanhf(kv * frow[tid] * scal);
        }
        __syncthreads();  // protect frow/cnt/buffers reuse next sample
    }
}

// =========================================================================
// launch
// =========================================================================
extern "C" void kernel_launch(void* const* d_in, const int* in_sizes, int n_in,
                              void* d_out, int out_size)
{
    const float* obs    = (const float*)d_in[0];
    const float* action = (const float*)d_in[1];
    const float* ow1 = (const float*)d_in[2];
    const float* ob1 = (const float*)d_in[3];
    const float* ow2 = (const float*)d_in[4];
    const float* ob2 = (const float*)d_in[5];
    const float* aw1 = (const float*)d_in[6];
    const float* ab1 = (const float*)d_in[7];
    const float* aw2 = (const float*)d_in[8];
    const float* ab2 = (const float*)d_in[9];
    const float* mw1 = (const float*)d_in[10];
    const float* mb1 = (const float*)d_in[11];
    const float* mw2 = (const float*)d_in[12];
    const float* mb2 = (const float*)d_in[13];
    const float* mw3 = (const float*)d_in[14];
    const float* mb3 = (const float*)d_in[15];
    const float* kw1 = (const float*)d_in[16];
    const float* kb1 = (const float*)d_in[17];
    const float* kw2 = (const float*)d_in[18];
    const float* kb2 = (const float*)d_in[19];
    const float* kw3 = (const float*)d_in[20];
    const float* kb3 = (const float*)d_in[21];
    float* out = (float*)d_out;

    cudaFuncSetAttribute(fwd_kernel, cudaFuncAttributeMaxDynamicSharedMemorySize,
                         FWD_SMEM_BYTES);
    cudaFuncSetAttribute(jac_kernel, cudaFuncAttributeMaxDynamicSharedMemorySize,
                         JAC_SMEM_BYTES);

    g_kernel<<<(COMP * COMP * 32 + 255) / 256, 256>>>(mw1);
    fwd_kernel<<<BATCH / TS, FWD_THREADS, FWD_SMEM_BYTES>>>(
        obs, action, ow1, ob1, ow2, ob2, aw1, ab1, aw2, ab2,
        mw1, mb1, mw2, mb2, mw3, mb3, kw1, kb1, kw2, kb2, kw3, kb3);
    jac_kernel<<<BATCH / SPC, 256, JAC_SMEM_BYTES>>>(mw2, mw3, out);
}